// round 4
// baseline (speedup 1.0000x reference)
#include <cuda_runtime.h>

#define N_NODES 100000
#define E_EDGES 1200000
#define F 64

#define SCAN_BLK 256
#define NPART ((N_NODES + SCAN_BLK - 1) / SCAN_BLK)   // 391

// ---------------- scratch (device globals; no allocation allowed) ----------
__device__ int   g_is64;
__device__ int   g_cnt[N_NODES];
__device__ int   g_cur[N_NODES];
__device__ int   g_off[N_NODES + 1];
__device__ int   g_part[NPART];
__device__ int   g_pscan[NPART];
__device__ int   g_srcs[E_EDGES];
__device__ __align__(16) float g_hbuf[2][N_NODES * F];

// ---------------- dtype detection ------------------------------------------
__global__ void detect_kernel(const int* __restrict__ ei32) {
    __shared__ int any;
    if (threadIdx.x == 0) any = 0;
    __syncthreads();
    int acc = 0;
    for (int i = threadIdx.x * 2 + 1; i < 4096; i += 2 * blockDim.x)
        acc |= ei32[i];
    if (acc) atomicOr(&any, 1);
    __syncthreads();
    if (threadIdx.x == 0) g_is64 = (any == 0) ? 1 : 0;
}

__device__ __forceinline__ int load_idx(const void* ei, long long pos, bool is64) {
    if (is64) return (int)((const long long*)ei)[pos];
    return ((const int*)ei)[pos];
}

// ---------------- CSR build -------------------------------------------------
__global__ void zero_kernel() {
    int i = blockIdx.x * blockDim.x + threadIdx.x;
    if (i < N_NODES) { g_cnt[i] = 0; g_cur[i] = 0; }
}

__global__ void count_kernel(const void* __restrict__ ei) {
    const bool is64 = (g_is64 != 0);
    int stride = gridDim.x * blockDim.x;
    for (int e = blockIdx.x * blockDim.x + threadIdx.x; e < E_EDGES; e += stride) {
        int d = load_idx(ei, (long long)E_EDGES + e, is64);
        if ((unsigned)d < (unsigned)N_NODES)
            atomicAdd(&g_cnt[d], 1);
    }
}

__global__ void part_sum_kernel() {
    __shared__ int red[SCAN_BLK];
    int i = blockIdx.x * SCAN_BLK + threadIdx.x;
    red[threadIdx.x] = (i < N_NODES) ? g_cnt[i] : 0;
    __syncthreads();
    for (int s = SCAN_BLK / 2; s > 0; s >>= 1) {
        if (threadIdx.x < s) red[threadIdx.x] += red[threadIdx.x + s];
        __syncthreads();
    }
    if (threadIdx.x == 0) g_part[blockIdx.x] = red[0];
}

__global__ void part_scan_kernel() {
    __shared__ int s[512];
    int t = threadIdx.x;
    int v = (t < NPART) ? g_part[t] : 0;
    s[t] = v;
    __syncthreads();
    for (int off = 1; off < 512; off <<= 1) {
        int u = (t >= off) ? s[t - off] : 0;
        __syncthreads();
        s[t] += u;
        __syncthreads();
    }
    if (t < NPART) g_pscan[t] = s[t] - v;
    if (t == 511) g_off[N_NODES] = s[511];
}

__global__ void offsets_kernel() {
    __shared__ int s[SCAN_BLK];
    int t = threadIdx.x;
    int i = blockIdx.x * SCAN_BLK + t;
    int v = (i < N_NODES) ? g_cnt[i] : 0;
    s[t] = v;
    __syncthreads();
    for (int off = 1; off < SCAN_BLK; off <<= 1) {
        int u = (t >= off) ? s[t - off] : 0;
        __syncthreads();
        s[t] += u;
        __syncthreads();
    }
    if (i < N_NODES) g_off[i] = g_pscan[blockIdx.x] + s[t] - v;
}

__global__ void fill_kernel(const void* __restrict__ ei) {
    const bool is64 = (g_is64 != 0);
    int stride = gridDim.x * blockDim.x;
    for (int e = blockIdx.x * blockDim.x + threadIdx.x; e < E_EDGES; e += stride) {
        int d = load_idx(ei, (long long)E_EDGES + e, is64);
        int s = load_idx(ei, (long long)e, is64);
        if ((unsigned)d < (unsigned)N_NODES && (unsigned)s < (unsigned)N_NODES) {
            int p = g_off[d] + atomicAdd(&g_cur[d], 1);
            g_srcs[p] = s;
        }
    }
}

// ---------------- fused layer: gather-aggregate + dual GEMM + bias (+tanh) --
__device__ __forceinline__ float fast_tanh(float x) {
    float e = __expf(2.f * x);
    return 1.f - 2.f / (e + 1.f);
}

#define LAYER_THREADS 256
#define TILE_NODES    128
#define ASTRIDE       65
#define WSTRIDE       66
#define LAYER_SMEM_FLOATS (2 * 64 * WSTRIDE + 2 * TILE_NODES * ASTRIDE)
#define LAYER_SMEM_BYTES  (LAYER_SMEM_FLOATS * 4)

__device__ __forceinline__ unsigned long long pack2(float v) {
    unsigned long long r;
    asm("mov.b64 %0, {%1, %1};" : "=l"(r) : "f"(v));
    return r;
}
__device__ __forceinline__ void ffma2(unsigned long long& acc, unsigned long long a,
                                      unsigned long long b) {
    asm("fma.rn.f32x2 %0, %1, %2, %0;" : "+l"(acc) : "l"(a), "l"(b));
}
__device__ __forceinline__ float2 unpack2(unsigned long long v) {
    float lo, hi;
    asm("mov.b64 {%0, %1}, %2;" : "=f"(lo), "=f"(hi) : "l"(v));
    return make_float2(lo, hi);
}

__global__ void __launch_bounds__(LAYER_THREADS, 2)
layer_kernel(const float* __restrict__ x, int hin_sel, int hout_sel,
             float* __restrict__ dout,
             const float* __restrict__ Wl, const float* __restrict__ bl,
             const float* __restrict__ Wr, int do_tanh) {
    extern __shared__ float sm[];
    float* wls = sm;                         // [64][WSTRIDE] k-major
    float* wrs = wls + 64 * WSTRIDE;
    float* as_ = wrs + 64 * WSTRIDE;         // [TILE_NODES][ASTRIDE] aggregated
    float* hs_ = as_ + TILE_NODES * ASTRIDE; // [TILE_NODES][ASTRIDE] self feats

    const float* __restrict__ hin = (hin_sel < 0) ? x : g_hbuf[hin_sel];
    float* __restrict__ hout = (hout_sel < 0) ? dout : g_hbuf[hout_sel];

    const int tid = threadIdx.x;
    const int base = blockIdx.x * TILE_NODES;

    // 1) weights: coalesced LDG, transposed STS
    for (int idx = tid; idx < 64 * 64; idx += LAYER_THREADS) {
        int f = idx >> 6, k = idx & 63;
        wls[k * WSTRIDE + f] = Wl[idx];
        wrs[k * WSTRIDE + f] = Wr[idx];
    }
    // 2) self-feature tile: float4 LDG
    for (int v = tid; v < TILE_NODES * 16; v += LAYER_THREADS) {
        int node = v >> 4, kq = (v & 15) * 4;
        int gn = base + node;
        float4 vh = make_float4(0.f, 0.f, 0.f, 0.f);
        if (gn < N_NODES)
            vh = *(const float4*)(hin + (size_t)gn * 64 + kq);
        float* hp = hs_ + node * ASTRIDE + kq;
        hp[0] = vh.x; hp[1] = vh.y; hp[2] = vh.z; hp[3] = vh.w;
    }

    // 3) gather-aggregate: 8 warps x 16 nodes, shfl-broadcast indices,
    //    8-wide unrolled row loads for MLP
    {
        const int wid = tid >> 5, lane = tid & 31;
        for (int n = wid * 16; n < wid * 16 + 16; n++) {
            int gn = base + n;
            float a0 = 0.f, a1 = 0.f;
            if (gn < N_NODES) {
                int p = g_off[gn], pe = g_off[gn + 1];
                while (p < pe) {
                    int cnt = pe - p; if (cnt > 32) cnt = 32;
                    int idx = (lane < cnt) ? g_srcs[p + lane] : 0;
                    int j = 0;
                    for (; j + 8 <= cnt; j += 8) {
                        int s[8];
                        #pragma unroll
                        for (int u = 0; u < 8; u++)
                            s[u] = __shfl_sync(0xffffffffu, idx, j + u);
                        float va[8], vb[8];
                        #pragma unroll
                        for (int u = 0; u < 8; u++) {
                            const float* r = hin + (size_t)s[u] * 64;
                            va[u] = r[lane]; vb[u] = r[lane + 32];
                        }
                        #pragma unroll
                        for (int u = 0; u < 8; u++) { a0 += va[u]; a1 += vb[u]; }
                    }
                    for (; j + 4 <= cnt; j += 4) {
                        int s[4];
                        #pragma unroll
                        for (int u = 0; u < 4; u++)
                            s[u] = __shfl_sync(0xffffffffu, idx, j + u);
                        float va[4], vb[4];
                        #pragma unroll
                        for (int u = 0; u < 4; u++) {
                            const float* r = hin + (size_t)s[u] * 64;
                            va[u] = r[lane]; vb[u] = r[lane + 32];
                        }
                        #pragma unroll
                        for (int u = 0; u < 4; u++) { a0 += va[u]; a1 += vb[u]; }
                    }
                    for (; j < cnt; j++) {
                        int s0 = __shfl_sync(0xffffffffu, idx, j);
                        const float* r = hin + (size_t)s0 * 64;
                        a0 += r[lane]; a1 += r[lane + 32];
                    }
                    p += cnt;
                }
            }
            as_[n * ASTRIDE + lane]      = a0;
            as_[n * ASTRIDE + 32 + lane] = a1;
        }
    }
    __syncthreads();

    // 4) dual GEMM: per thread 4 nodes x 8 outputs, FFMA2 accumulators
    const int fx = tid & 7;
    const int ny = tid >> 3;          // 0..31
    const int f0 = fx * 8;
    const int n0 = ny * 4;

    unsigned long long acc[4][4];
    #pragma unroll
    for (int n = 0; n < 4; n++)
        #pragma unroll
        for (int jp = 0; jp < 4; jp++) acc[n][jp] = 0ull;

    #pragma unroll 8
    for (int k = 0; k < 64; k++) {
        const unsigned long long* wl64 =
            (const unsigned long long*)(wls + k * WSTRIDE + f0);
        const unsigned long long* wr64 =
            (const unsigned long long*)(wrs + k * WSTRIDE + f0);
        unsigned long long wl[4], wr[4];
        #pragma unroll
        for (int jp = 0; jp < 4; jp++) { wl[jp] = wl64[jp]; wr[jp] = wr64[jp]; }

        const float* ab = as_ + n0 * ASTRIDE + k;
        const float* hb = hs_ + n0 * ASTRIDE + k;
        #pragma unroll
        for (int n = 0; n < 4; n++) {
            unsigned long long a2 = pack2(ab[n * ASTRIDE]);
            unsigned long long h2 = pack2(hb[n * ASTRIDE]);
            #pragma unroll
            for (int jp = 0; jp < 4; jp++) {
                ffma2(acc[n][jp], a2, wl[jp]);
                ffma2(acc[n][jp], h2, wr[jp]);
            }
        }
    }

    float bias[8];
    #pragma unroll
    for (int j = 0; j < 8; j++) bias[j] = bl[f0 + j];

    #pragma unroll
    for (int n = 0; n < 4; n++) {
        int gn = base + n0 + n;
        if (gn >= N_NODES) continue;
        float v[8];
        #pragma unroll
        for (int jp = 0; jp < 4; jp++) {
            float2 p = unpack2(acc[n][jp]);
            v[2 * jp]     = p.x + bias[2 * jp];
            v[2 * jp + 1] = p.y + bias[2 * jp + 1];
        }
        if (do_tanh) {
            #pragma unroll
            for (int j = 0; j < 8; j++) v[j] = fast_tanh(v[j]);
        }
        float* op = hout + (size_t)gn * 64 + f0;
        *(float4*)(op)     = make_float4(v[0], v[1], v[2], v[3]);
        *(float4*)(op + 4) = make_float4(v[4], v[5], v[6], v[7]);
    }
}

// ---------------- launch -----------------------------------------------------
extern "C" void kernel_launch(void* const* d_in, const int* in_sizes, int n_in,
                              void* d_out, int out_size) {
    const float* x      = (const float*)d_in[0];
    const void*  ei     = d_in[1];
    const float* Wl_in  = (const float*)d_in[2];
    const float* bl_in  = (const float*)d_in[3];
    const float* Wr_in  = (const float*)d_in[4];
    const float* Wl_med = (const float*)d_in[5];
    const float* bl_med = (const float*)d_in[6];
    const float* Wr_med = (const float*)d_in[7];
    const float* Wl_out = (const float*)d_in[8];
    const float* bl_out = (const float*)d_in[9];
    const float* Wr_out = (const float*)d_in[10];
    float*       out    = (float*)d_out;

    static int smem_set = 0;
    if (!smem_set) {
        cudaFuncSetAttribute(layer_kernel,
                             cudaFuncAttributeMaxDynamicSharedMemorySize,
                             LAYER_SMEM_BYTES);
        smem_set = 1;
    }

    // CSR build (structure shared by all 4 layers)
    detect_kernel<<<1, 256>>>((const int*)ei);
    zero_kernel<<<(N_NODES + 255) / 256, 256>>>();
    count_kernel<<<1024, 256>>>(ei);
    part_sum_kernel<<<NPART, SCAN_BLK>>>();
    part_scan_kernel<<<1, 512>>>();
    offsets_kernel<<<NPART, SCAN_BLK>>>();
    fill_kernel<<<1024, 256>>>(ei);

    const int BLOCKS = (N_NODES + TILE_NODES - 1) / TILE_NODES;  // 782

    layer_kernel<<<BLOCKS, LAYER_THREADS, LAYER_SMEM_BYTES>>>(
        x, -1, 0, nullptr, Wl_in, bl_in, Wr_in, 1);
    layer_kernel<<<BLOCKS, LAYER_THREADS, LAYER_SMEM_BYTES>>>(
        nullptr, 0, 1, nullptr, Wl_med, bl_med, Wr_med, 1);
    layer_kernel<<<BLOCKS, LAYER_THREADS, LAYER_SMEM_BYTES>>>(
        nullptr, 1, 0, nullptr, Wl_med, bl_med, Wr_med, 1);
    layer_kernel<<<BLOCKS, LAYER_THREADS, LAYER_SMEM_BYTES>>>(
        nullptr, 0, -1, out, Wl_out, bl_out, Wr_out, 0);
}

// round 5
// speedup vs baseline: 1.4757x; 1.4757x over previous
#include <cuda_runtime.h>

#define N_NODES 100000
#define E_EDGES 1200000
#define F 64

#define SCAN_BLK 256
#define NPART ((N_NODES + SCAN_BLK - 1) / SCAN_BLK)   // 391

// ---------------- scratch (device globals; no allocation allowed) ----------
__device__ int   g_is64;
__device__ int   g_cnt[N_NODES];
__device__ int   g_cur[N_NODES];
__device__ int   g_off[N_NODES + 1];
__device__ int   g_part[NPART];
__device__ int   g_pscan[NPART];
__device__ int   g_srcs[E_EDGES];
__device__ __align__(16) float g_agg[N_NODES * F];
__device__ __align__(16) float g_hbuf[2][N_NODES * F];

// ---------------- dtype detection ------------------------------------------
__global__ void detect_kernel(const int* __restrict__ ei32) {
    __shared__ int any;
    if (threadIdx.x == 0) any = 0;
    __syncthreads();
    int acc = 0;
    for (int i = threadIdx.x * 2 + 1; i < 4096; i += 2 * blockDim.x)
        acc |= ei32[i];
    if (acc) atomicOr(&any, 1);
    __syncthreads();
    if (threadIdx.x == 0) g_is64 = (any == 0) ? 1 : 0;
}

__device__ __forceinline__ int load_idx(const void* ei, long long pos, bool is64) {
    if (is64) return (int)((const long long*)ei)[pos];
    return ((const int*)ei)[pos];
}

// ---------------- CSR build -------------------------------------------------
__global__ void zero_kernel() {
    int i = blockIdx.x * blockDim.x + threadIdx.x;
    if (i < N_NODES) { g_cnt[i] = 0; g_cur[i] = 0; }
}

__global__ void count_kernel(const void* __restrict__ ei) {
    const bool is64 = (g_is64 != 0);
    int stride = gridDim.x * blockDim.x;
    for (int e = blockIdx.x * blockDim.x + threadIdx.x; e < E_EDGES; e += stride) {
        int d = load_idx(ei, (long long)E_EDGES + e, is64);
        if ((unsigned)d < (unsigned)N_NODES)
            atomicAdd(&g_cnt[d], 1);
    }
}

__global__ void part_sum_kernel() {
    __shared__ int red[SCAN_BLK];
    int i = blockIdx.x * SCAN_BLK + threadIdx.x;
    red[threadIdx.x] = (i < N_NODES) ? g_cnt[i] : 0;
    __syncthreads();
    for (int s = SCAN_BLK / 2; s > 0; s >>= 1) {
        if (threadIdx.x < s) red[threadIdx.x] += red[threadIdx.x + s];
        __syncthreads();
    }
    if (threadIdx.x == 0) g_part[blockIdx.x] = red[0];
}

__global__ void part_scan_kernel() {
    __shared__ int s[512];
    int t = threadIdx.x;
    int v = (t < NPART) ? g_part[t] : 0;
    s[t] = v;
    __syncthreads();
    for (int off = 1; off < 512; off <<= 1) {
        int u = (t >= off) ? s[t - off] : 0;
        __syncthreads();
        s[t] += u;
        __syncthreads();
    }
    if (t < NPART) g_pscan[t] = s[t] - v;
    if (t == 511) g_off[N_NODES] = s[511];
}

__global__ void offsets_kernel() {
    __shared__ int s[SCAN_BLK];
    int t = threadIdx.x;
    int i = blockIdx.x * SCAN_BLK + t;
    int v = (i < N_NODES) ? g_cnt[i] : 0;
    s[t] = v;
    __syncthreads();
    for (int off = 1; off < SCAN_BLK; off <<= 1) {
        int u = (t >= off) ? s[t - off] : 0;
        __syncthreads();
        s[t] += u;
        __syncthreads();
    }
    if (i < N_NODES) g_off[i] = g_pscan[blockIdx.x] + s[t] - v;
}

__global__ void fill_kernel(const void* __restrict__ ei) {
    const bool is64 = (g_is64 != 0);
    int stride = gridDim.x * blockDim.x;
    for (int e = blockIdx.x * blockDim.x + threadIdx.x; e < E_EDGES; e += stride) {
        int d = load_idx(ei, (long long)E_EDGES + e, is64);
        int s = load_idx(ei, (long long)e, is64);
        if ((unsigned)d < (unsigned)N_NODES && (unsigned)s < (unsigned)N_NODES) {
            int p = g_off[d] + atomicAdd(&g_cur[d], 1);
            g_srcs[p] = s;
        }
    }
}

// ---------------- aggregation: one warp per node, deep-MLP gather ----------
__global__ void __launch_bounds__(256)
agg_kernel(const float* __restrict__ x, int hin_sel) {
    const float* __restrict__ h = (hin_sel < 0) ? x : g_hbuf[hin_sel];
    int w = (blockIdx.x * blockDim.x + threadIdx.x) >> 5;
    int lane = threadIdx.x & 31;
    if (w >= N_NODES) return;

    float a0 = 0.f, a1 = 0.f;
    int p = g_off[w], pe = g_off[w + 1];
    while (p < pe) {
        int cnt = pe - p; if (cnt > 32) cnt = 32;
        int idx = (lane < cnt) ? g_srcs[p + lane] : 0;   // coalesced index load
        int j = 0;
        for (; j + 8 <= cnt; j += 8) {
            int s[8];
            #pragma unroll
            for (int u = 0; u < 8; u++)
                s[u] = __shfl_sync(0xffffffffu, idx, j + u);
            float va[8], vb[8];
            #pragma unroll
            for (int u = 0; u < 8; u++) {               // 16 loads in flight
                const float* r = h + (size_t)s[u] * 64;
                va[u] = r[lane]; vb[u] = r[lane + 32];
            }
            #pragma unroll
            for (int u = 0; u < 8; u++) { a0 += va[u]; a1 += vb[u]; }
        }
        for (; j + 4 <= cnt; j += 4) {
            int s[4];
            #pragma unroll
            for (int u = 0; u < 4; u++)
                s[u] = __shfl_sync(0xffffffffu, idx, j + u);
            float va[4], vb[4];
            #pragma unroll
            for (int u = 0; u < 4; u++) {
                const float* r = h + (size_t)s[u] * 64;
                va[u] = r[lane]; vb[u] = r[lane + 32];
            }
            #pragma unroll
            for (int u = 0; u < 4; u++) { a0 += va[u]; a1 += vb[u]; }
        }
        for (; j < cnt; j++) {
            int s0 = __shfl_sync(0xffffffffu, idx, j);
            const float* r = h + (size_t)s0 * 64;
            a0 += r[lane]; a1 += r[lane + 32];
        }
        p += cnt;
    }
    g_agg[(size_t)w * F + lane]      = a0;
    g_agg[(size_t)w * F + lane + 32] = a1;
}

// ---------------- fused dual-GEMM + bias (+tanh), FFMA2 path ----------------
__device__ __forceinline__ float fast_tanh(float x) {
    float e = __expf(2.f * x);
    return 1.f - 2.f / (e + 1.f);
}

#define LIN_THREADS 128
#define TILE_NODES  128
#define ASTRIDE     65
#define WSTRIDE     66
#define LIN_SMEM_FLOATS (2 * 64 * WSTRIDE + 2 * TILE_NODES * ASTRIDE)

__device__ __forceinline__ unsigned long long pack2(float v) {
    unsigned long long r;
    asm("mov.b64 %0, {%1, %1};" : "=l"(r) : "f"(v));
    return r;
}
__device__ __forceinline__ void ffma2(unsigned long long& acc, unsigned long long a,
                                      unsigned long long b) {
    asm("fma.rn.f32x2 %0, %1, %2, %0;" : "+l"(acc) : "l"(a), "l"(b));
}
__device__ __forceinline__ float2 unpack2(unsigned long long v) {
    float lo, hi;
    asm("mov.b64 {%0, %1}, %2;" : "=f"(lo), "=f"(hi) : "l"(v));
    return make_float2(lo, hi);
}

__global__ void __launch_bounds__(LIN_THREADS)
lin_kernel(const float* __restrict__ x, int hin_sel, int hout_sel,
           float* __restrict__ dout,
           const float* __restrict__ Wl, const float* __restrict__ bl,
           const float* __restrict__ Wr, int do_tanh) {
    extern __shared__ float sm[];
    float* wls = sm;                          // [64][WSTRIDE] k-major
    float* wrs = wls + 64 * WSTRIDE;
    float* as_ = wrs + 64 * WSTRIDE;          // [TILE_NODES][ASTRIDE]
    float* hs_ = as_ + TILE_NODES * ASTRIDE;

    const float* __restrict__ hin = (hin_sel < 0) ? x : g_hbuf[hin_sel];
    float* __restrict__ hout = (hout_sel < 0) ? dout : g_hbuf[hout_sel];

    for (int idx = threadIdx.x; idx < 64 * 64; idx += LIN_THREADS) {
        int f = idx >> 6, k = idx & 63;
        wls[k * WSTRIDE + f] = Wl[idx];
        wrs[k * WSTRIDE + f] = Wr[idx];
    }

    const int base = blockIdx.x * TILE_NODES;
    for (int v = threadIdx.x; v < TILE_NODES * 16; v += LIN_THREADS) {
        int node = v >> 4, kq = (v & 15) * 4;
        int gn = base + node;
        float4 va = make_float4(0.f, 0.f, 0.f, 0.f);
        float4 vh = va;
        if (gn < N_NODES) {
            va = *(const float4*)(g_agg + (size_t)gn * 64 + kq);
            vh = *(const float4*)(hin   + (size_t)gn * 64 + kq);
        }
        float* ap = as_ + node * ASTRIDE + kq;
        ap[0] = va.x; ap[1] = va.y; ap[2] = va.z; ap[3] = va.w;
        float* hp = hs_ + node * ASTRIDE + kq;
        hp[0] = vh.x; hp[1] = vh.y; hp[2] = vh.z; hp[3] = vh.w;
    }
    __syncthreads();

    const int fx = threadIdx.x & 7;
    const int ny = threadIdx.x >> 3;
    const int f0 = fx * 8;
    const int n0 = ny * 8;

    unsigned long long acc[8][4];
    #pragma unroll
    for (int n = 0; n < 8; n++)
        #pragma unroll
        for (int jp = 0; jp < 4; jp++) acc[n][jp] = 0ull;

    #pragma unroll 8
    for (int k = 0; k < 64; k++) {
        const unsigned long long* wl64 =
            (const unsigned long long*)(wls + k * WSTRIDE + f0);
        const unsigned long long* wr64 =
            (const unsigned long long*)(wrs + k * WSTRIDE + f0);
        unsigned long long wl[4], wr[4];
        #pragma unroll
        for (int jp = 0; jp < 4; jp++) { wl[jp] = wl64[jp]; wr[jp] = wr64[jp]; }

        const float* ab = as_ + n0 * ASTRIDE + k;
        const float* hb = hs_ + n0 * ASTRIDE + k;
        #pragma unroll
        for (int n = 0; n < 8; n++) {
            unsigned long long a2 = pack2(ab[n * ASTRIDE]);
            unsigned long long h2 = pack2(hb[n * ASTRIDE]);
            #pragma unroll
            for (int jp = 0; jp < 4; jp++) {
                ffma2(acc[n][jp], a2, wl[jp]);
                ffma2(acc[n][jp], h2, wr[jp]);
            }
        }
    }

    float bias[8];
    #pragma unroll
    for (int j = 0; j < 8; j++) bias[j] = bl[f0 + j];

    #pragma unroll
    for (int n = 0; n < 8; n++) {
        int gn = base + n0 + n;
        if (gn >= N_NODES) continue;
        float v[8];
        #pragma unroll
        for (int jp = 0; jp < 4; jp++) {
            float2 p = unpack2(acc[n][jp]);
            v[2 * jp]     = p.x + bias[2 * jp];
            v[2 * jp + 1] = p.y + bias[2 * jp + 1];
        }
        if (do_tanh) {
            #pragma unroll
            for (int j = 0; j < 8; j++) v[j] = fast_tanh(v[j]);
        }
        float* op = hout + (size_t)gn * 64 + f0;
        *(float4*)(op)     = make_float4(v[0], v[1], v[2], v[3]);
        *(float4*)(op + 4) = make_float4(v[4], v[5], v[6], v[7]);
    }
}

// ---------------- launch -----------------------------------------------------
extern "C" void kernel_launch(void* const* d_in, const int* in_sizes, int n_in,
                              void* d_out, int out_size) {
    const float* x      = (const float*)d_in[0];
    const void*  ei     = d_in[1];
    const float* Wl_in  = (const float*)d_in[2];
    const float* bl_in  = (const float*)d_in[3];
    const float* Wr_in  = (const float*)d_in[4];
    const float* Wl_med = (const float*)d_in[5];
    const float* bl_med = (const float*)d_in[6];
    const float* Wr_med = (const float*)d_in[7];
    const float* Wl_out = (const float*)d_in[8];
    const float* bl_out = (const float*)d_in[9];
    const float* Wr_out = (const float*)d_in[10];
    float*       out    = (float*)d_out;

    static int smem_set = 0;
    const int LIN_SMEM = LIN_SMEM_FLOATS * 4;   // 100,352 bytes
    if (!smem_set) {
        cudaFuncSetAttribute(lin_kernel,
                             cudaFuncAttributeMaxDynamicSharedMemorySize, LIN_SMEM);
        smem_set = 1;
    }

    // CSR build
    detect_kernel<<<1, 256>>>((const int*)ei);
    zero_kernel<<<(N_NODES + 255) / 256, 256>>>();
    count_kernel<<<1024, 256>>>(ei);
    part_sum_kernel<<<NPART, SCAN_BLK>>>();
    part_scan_kernel<<<1, 512>>>();
    offsets_kernel<<<NPART, SCAN_BLK>>>();
    fill_kernel<<<1024, 256>>>(ei);

    const int AGG_BLOCKS = (N_NODES * 32 + 255) / 256;      // 1 warp / node
    const int LIN_BLOCKS = (N_NODES + TILE_NODES - 1) / TILE_NODES;  // 782

    agg_kernel<<<AGG_BLOCKS, 256>>>(x, -1);
    lin_kernel<<<LIN_BLOCKS, LIN_THREADS, LIN_SMEM>>>(x, -1, 0, nullptr,
                                                      Wl_in, bl_in, Wr_in, 1);
    agg_kernel<<<AGG_BLOCKS, 256>>>(nullptr, 0);
    lin_kernel<<<LIN_BLOCKS, LIN_THREADS, LIN_SMEM>>>(nullptr, 0, 1, nullptr,
                                                      Wl_med, bl_med, Wr_med, 1);
    agg_kernel<<<AGG_BLOCKS, 256>>>(nullptr, 1);
    lin_kernel<<<LIN_BLOCKS, LIN_THREADS, LIN_SMEM>>>(nullptr, 1, 0, nullptr,
                                                      Wl_med, bl_med, Wr_med, 1);
    agg_kernel<<<AGG_BLOCKS, 256>>>(nullptr, 0);
    lin_kernel<<<LIN_BLOCKS, LIN_THREADS, LIN_SMEM>>>(nullptr, 0, -1, out,
                                                      Wl_out, bl_out, Wr_out, 0);
}